// round 1
// baseline (speedup 1.0000x reference)
#include <cuda_runtime.h>
#include <cstdint>
#include <cstddef>

#define NS     10
#define NPROJ  32
#define CCH    64
#define DD     9
#define DOUTD  4
#define PP1    2
#define PP2    4
#define PP3    4
#define PTOT   (PP1 + PP2 + PP3)
#define NT1    9
#define NT2    45
#define NT3    165
#define NT     (NT1 + NT2 + NT3)   // 219

#define CPB    8                   // channels per block
#define NPB    64                  // nodes per block
#define XS_STRIDE 66               // padded node stride (floats), 8B aligned

#define SMEM_COEF_F2     (CPB * NT * DOUTD)            // 7008 float2
#define SMEM_COEF_BYTES  (SMEM_COEF_F2 * 8)            // 56064
#define SMEM_XS_FLOATS   (CPB * DD * XS_STRIDE)        // 4752
#define SMEM_BYTES       (SMEM_COEF_BYTES + SMEM_XS_FLOATS * 4)  // 75072

typedef unsigned long long ull;

// Symmetrized coefficient table: [s][c][t][u], each float2 = (v, v) duplicated
__device__ float2 g_Acoef[NS * CCH * NT * DOUTD];

__device__ __forceinline__ ull fmul2(ull a, ull b) {
    ull d; asm("mul.rn.f32x2 %0, %1, %2;" : "=l"(d) : "l"(a), "l"(b)); return d;
}
__device__ __forceinline__ ull ffma2(ull a, ull b, ull c) {
    ull d; asm("fma.rn.f32x2 %0, %1, %2, %3;" : "=l"(d) : "l"(a), "l"(b), "l"(c)); return d;
}
__device__ __forceinline__ float2 unpack2(ull v) {
    unsigned lo, hi; asm("mov.b64 {%0, %1}, %2;" : "=r"(lo), "=r"(hi) : "l"(v));
    return make_float2(__uint_as_float(lo), __uint_as_float(hi));
}

__device__ __forceinline__ int findSpecies(const int* __restrict__ counts, int n) {
    int acc = 0, s = 0;
    #pragma unroll
    for (int q = 0; q < NS; q++) {
        acc += counts[q];
        if (n >= acc) s = q + 1;
    }
    return (s < NS) ? s : (NS - 1);
}

// ---------------------------------------------------------------------------
// Prep: build symmetrized coefficients  A[s][c][t][u] = sum_p usym[u,t,p]*wp[s,deg_p,c]
// grid = NS*CCH blocks, 256 threads
// ---------------------------------------------------------------------------
__global__ void prep_kernel(const float* __restrict__ w,
                            const float* __restrict__ proj,
                            const float* __restrict__ u1,
                            const float* __restrict__ u2,
                            const float* __restrict__ u3) {
    int s = blockIdx.x / CCH;
    int c = blockIdx.x % CCH;
    __shared__ float wpv[PTOT];
    int tid = threadIdx.x;
    if (tid < PTOT) {
        float acc = 0.f;
        for (int a = 0; a < NPROJ; a++)
            acc += w[((size_t)s * NPROJ + a) * CCH + c] * proj[a * PTOT + tid];
        wpv[tid] = acc;
    }
    __syncthreads();

    for (int t = tid; t < NT; t += blockDim.x) {
        float cv[DOUTD];
        if (t < NT1) {
            int i = t;
            #pragma unroll
            for (int u = 0; u < DOUTD; u++) {
                float acc = 0.f;
                for (int p = 0; p < PP1; p++)
                    acc += u1[((size_t)u * DD + i) * PP1 + p] * wpv[p];
                cv[u] = acc;
            }
        } else if (t < NT1 + NT2) {
            int q = t - NT1;
            int i = 0, cnt = DD;
            while (q >= cnt) { q -= cnt; i++; cnt--; }
            int j = i + q;
            #pragma unroll
            for (int u = 0; u < DOUTD; u++) {
                float acc = 0.f;
                for (int p = 0; p < PP2; p++) {
                    float sym = u2[(((size_t)u * DD + i) * DD + j) * PP2 + p];
                    if (i != j) sym += u2[(((size_t)u * DD + j) * DD + i) * PP2 + p];
                    acc += sym * wpv[PP1 + p];
                }
                cv[u] = acc;
            }
        } else {
            int q = t - NT1 - NT2;
            int i = 0;
            for (;;) {
                int m = DD - i;
                int cnt = m * (m + 1) / 2;
                if (q < cnt) break;
                q -= cnt; i++;
            }
            int j = i;
            for (;;) {
                int cnt = DD - j;
                if (q < cnt) break;
                q -= cnt; j++;
            }
            int k = j + q;
            int pa[6], pb[6], pc[6], np = 0;
            if (i == j && j == k) {
                pa[0]=i; pb[0]=i; pc[0]=i; np = 1;
            } else if (i == j) {
                pa[0]=i; pb[0]=i; pc[0]=k;
                pa[1]=i; pb[1]=k; pc[1]=i;
                pa[2]=k; pb[2]=i; pc[2]=i; np = 3;
            } else if (j == k) {
                pa[0]=i; pb[0]=j; pc[0]=j;
                pa[1]=j; pb[1]=i; pc[1]=j;
                pa[2]=j; pb[2]=j; pc[2]=i; np = 3;
            } else {
                pa[0]=i; pb[0]=j; pc[0]=k;
                pa[1]=i; pb[1]=k; pc[1]=j;
                pa[2]=j; pb[2]=i; pc[2]=k;
                pa[3]=j; pb[3]=k; pc[3]=i;
                pa[4]=k; pb[4]=i; pc[4]=j;
                pa[5]=k; pb[5]=j; pc[5]=i; np = 6;
            }
            #pragma unroll
            for (int u = 0; u < DOUTD; u++) {
                float acc = 0.f;
                for (int m = 0; m < np; m++) {
                    const float* up = u3 + ((((size_t)u * DD + pa[m]) * DD + pb[m]) * DD + pc[m]) * PP3;
                    for (int p = 0; p < PP3; p++)
                        acc += up[p] * wpv[PP1 + PP2 + p];
                }
                cv[u] = acc;
            }
        }
        float2* dst = g_Acoef + (((size_t)(s * CCH + c)) * NT + t) * DOUTD;
        #pragma unroll
        for (int u = 0; u < DOUTD; u++) dst[u] = make_float2(cv[u], cv[u]);
    }
}

// ---------------------------------------------------------------------------
// Main: grid = (ceil(N/64), 8), 256 threads.
// Warp = one channel, 32 lanes x 2 packed nodes. Coefficients smem-broadcast.
// ---------------------------------------------------------------------------
__global__ __launch_bounds__(256) void main_kernel(
    const float* __restrict__ x,
    const int* __restrict__ counts,
    float* __restrict__ out, int N)
{
    extern __shared__ char smemRaw[];
    float2* coefS = (float2*)smemRaw;
    float*  xsS   = (float*)(smemRaw + SMEM_COEF_BYTES);

    const int n0  = blockIdx.x * NPB;
    const int c0  = blockIdx.y * CPB;
    const int tid = threadIdx.x;

    int nLast = n0 + NPB - 1;
    if (nLast > N - 1) nLast = N - 1;
    const int sA = findSpecies(counts, n0);
    const int sB = findSpecies(counts, nLast);
    const bool fast = (sA == sB) && (n0 + NPB <= N);

    // Stage x: xs[cc][i][node], conflict-free writes (stride 66) and paired reads
    for (int idx = tid; idx < NPB * CPB * DD; idx += 256) {
        int n  = idx / (CPB * DD);
        int r  = idx % (CPB * DD);
        int cc = r / DD;
        int i  = r % DD;
        int gn = n0 + n;
        float v = (gn < N) ? x[((size_t)gn * CCH + (c0 + cc)) * DD + i] : 0.f;
        xsS[(cc * DD + i) * XS_STRIDE + n] = v;
    }
    if (fast) {
        const float4* src = (const float4*)(g_Acoef + ((size_t)(sA * CCH + c0)) * NT * DOUTD);
        float4* dst = (float4*)coefS;
        for (int idx = tid; idx < SMEM_COEF_F2 / 2; idx += 256) dst[idx] = src[idx];
    }
    __syncthreads();

    const int wslot = tid >> 5;
    const int lane  = tid & 31;
    const int c     = c0 + wslot;

    if (fast) {
        // Packed operands: lo half = node n0+2*lane, hi half = node n0+2*lane+1
        ull xv[DD];
        const float* xb = xsS + wslot * DD * XS_STRIDE + 2 * lane;
        #pragma unroll
        for (int i = 0; i < DD; i++)
            xv[i] = *(const ull*)(xb + i * XS_STRIDE);

        const float2* cf = coefS + (size_t)wslot * NT * DOUTD;
        ull acc0 = 0, acc1 = 0, acc2 = 0, acc3 = 0;
        int t2 = NT1, t3 = NT1 + NT2;
        #pragma unroll
        for (int i = 0; i < DD; i++) {
            {
                const ulonglong2* cp = (const ulonglong2*)(cf + i * DOUTD);
                ulonglong2 lo = cp[0], hi = cp[1];
                acc0 = ffma2(xv[i], lo.x, acc0);
                acc1 = ffma2(xv[i], lo.y, acc1);
                acc2 = ffma2(xv[i], hi.x, acc2);
                acc3 = ffma2(xv[i], hi.y, acc3);
            }
            #pragma unroll
            for (int j = i; j < DD; j++) {
                ull pij = fmul2(xv[i], xv[j]);
                {
                    const ulonglong2* cp = (const ulonglong2*)(cf + t2 * DOUTD);
                    ulonglong2 lo = cp[0], hi = cp[1];
                    acc0 = ffma2(pij, lo.x, acc0);
                    acc1 = ffma2(pij, lo.y, acc1);
                    acc2 = ffma2(pij, hi.x, acc2);
                    acc3 = ffma2(pij, hi.y, acc3);
                }
                t2++;
                #pragma unroll
                for (int k = j; k < DD; k++) {
                    ull m = fmul2(pij, xv[k]);
                    const ulonglong2* cp = (const ulonglong2*)(cf + t3 * DOUTD);
                    ulonglong2 lo = cp[0], hi = cp[1];
                    acc0 = ffma2(m, lo.x, acc0);
                    acc1 = ffma2(m, lo.y, acc1);
                    acc2 = ffma2(m, hi.x, acc2);
                    acc3 = ffma2(m, hi.y, acc3);
                    t3++;
                }
            }
        }
        float2 a0 = unpack2(acc0), a1 = unpack2(acc1), a2 = unpack2(acc2), a3 = unpack2(acc3);
        const int nA = n0 + 2 * lane;
        const int nB = nA + 1;
        float4* outp = (float4*)out;
        outp[(size_t)nA * CCH + c] = make_float4(a0.x, a1.x, a2.x, a3.x);
        outp[(size_t)nB * CCH + c] = make_float4(a0.y, a1.y, a2.y, a3.y);
    } else {
        // Cold path: boundary / partial blocks. Scalar, coefficients from L2.
        for (int h = 0; h < 2; h++) {
            int n = n0 + 2 * lane + h;
            if (n >= N) continue;
            int s = findSpecies(counts, n);
            const float2* cf = g_Acoef + ((size_t)(s * CCH + c)) * NT * DOUTD;
            float xv[DD];
            const float* xb = xsS + wslot * DD * XS_STRIDE + (2 * lane + h);
            #pragma unroll
            for (int i = 0; i < DD; i++) xv[i] = xb[i * XS_STRIDE];
            float a[DOUTD] = {0.f, 0.f, 0.f, 0.f};
            int t2 = NT1, t3 = NT1 + NT2;
            #pragma unroll 1
            for (int i = 0; i < DD; i++) {
                #pragma unroll
                for (int u = 0; u < DOUTD; u++) a[u] += cf[i * DOUTD + u].x * xv[i];
                #pragma unroll 1
                for (int j = i; j < DD; j++) {
                    float pij = xv[i] * xv[j];
                    #pragma unroll
                    for (int u = 0; u < DOUTD; u++) a[u] += cf[t2 * DOUTD + u].x * pij;
                    t2++;
                    #pragma unroll 1
                    for (int k = j; k < DD; k++) {
                        float m = pij * xv[k];
                        #pragma unroll
                        for (int u = 0; u < DOUTD; u++) a[u] += cf[t3 * DOUTD + u].x * m;
                        t3++;
                    }
                }
            }
            float4* outp = (float4*)out;
            outp[(size_t)n * CCH + c] = make_float4(a[0], a[1], a[2], a[3]);
        }
    }
}

extern "C" void kernel_launch(void* const* d_in, const int* in_sizes, int n_in,
                              void* d_out, int out_size) {
    const float* x     = (const float*)d_in[0];
    const float* w     = (const float*)d_in[1];
    const float* proj  = (const float*)d_in[2];
    const float* u1    = (const float*)d_in[3];
    const float* u2    = (const float*)d_in[4];
    const float* u3    = (const float*)d_in[5];
    const int*   cnts  = (const int*)d_in[6];
    float* out = (float*)d_out;

    int N = in_sizes[0] / (CCH * DD);

    cudaFuncSetAttribute(main_kernel, cudaFuncAttributeMaxDynamicSharedMemorySize, SMEM_BYTES);

    prep_kernel<<<NS * CCH, 256>>>(w, proj, u1, u2, u3);

    dim3 grid((N + NPB - 1) / NPB, CCH / CPB);
    main_kernel<<<grid, 256, SMEM_BYTES>>>(x, cnts, out, N);
}

// round 2
// speedup vs baseline: 1.4229x; 1.4229x over previous
#include <cuda_runtime.h>
#include <cstdint>
#include <cstddef>

#define NS     10
#define NPROJ  32
#define CCH    64
#define DD     9
#define DOUTD  4
#define PP1    2
#define PP2    4
#define PP3    4
#define PTOT   (PP1 + PP2 + PP3)
#define NT1    9
#define NT2    45
#define NT3    165
#define NT     (NT1 + NT2 + NT3)   // 219

#define CPB      4                 // channels per block (1 warp per channel)
#define NPB      128               // nodes per block (4 per thread)
#define NPAIRS   (NPB / 2)         // 64 node-pairs
#define PAIR_W   18                // floats per (pair, i-contiguous) row chunk: 9 ull
#define THREADS  128

#define SMEM_COEF_F2     (CPB * NT * DOUTD)                  // 3504 float2
#define SMEM_COEF_BYTES  (SMEM_COEF_F2 * 8)                  // 28032
#define SMEM_XS_FLOATS   (CPB * NPAIRS * PAIR_W)             // 4608
#define SMEM_BYTES       (SMEM_COEF_BYTES + SMEM_XS_FLOATS * 4)  // 46464

#define OUT_NODE_W 20              // outStage words per node (16 data + 4 pad)

typedef unsigned long long ull;

// Symmetrized coefficient table: [s][c][t][u], each float2 = (v, v) duplicated
__device__ float2 g_Acoef[NS * CCH * NT * DOUTD];

__device__ __forceinline__ ull fmul2(ull a, ull b) {
    ull d; asm("mul.rn.f32x2 %0, %1, %2;" : "=l"(d) : "l"(a), "l"(b)); return d;
}
__device__ __forceinline__ ull ffma2(ull a, ull b, ull c) {
    ull d; asm("fma.rn.f32x2 %0, %1, %2, %3;" : "=l"(d) : "l"(a), "l"(b), "l"(c)); return d;
}
__device__ __forceinline__ float2 unpack2(ull v) {
    unsigned lo, hi; asm("mov.b64 {%0, %1}, %2;" : "=r"(lo), "=r"(hi) : "l"(v));
    return make_float2(__uint_as_float(lo), __uint_as_float(hi));
}

__device__ __forceinline__ int findSpecies(const int* __restrict__ counts, int n) {
    int acc = 0, s = 0;
    #pragma unroll
    for (int q = 0; q < NS; q++) {
        acc += counts[q];
        if (n >= acc) s = q + 1;
    }
    return (s < NS) ? s : (NS - 1);
}

// ---------------------------------------------------------------------------
// Prep: build symmetrized coefficients  A[s][c][t][u] = sum_p usym[u,t,p]*wp[s,deg_p,c]
// ---------------------------------------------------------------------------
__global__ void prep_kernel(const float* __restrict__ w,
                            const float* __restrict__ proj,
                            const float* __restrict__ u1,
                            const float* __restrict__ u2,
                            const float* __restrict__ u3) {
    int s = blockIdx.x / CCH;
    int c = blockIdx.x % CCH;
    __shared__ float wpv[PTOT];
    int tid = threadIdx.x;
    if (tid < PTOT) {
        float acc = 0.f;
        for (int a = 0; a < NPROJ; a++)
            acc += w[((size_t)s * NPROJ + a) * CCH + c] * proj[a * PTOT + tid];
        wpv[tid] = acc;
    }
    __syncthreads();

    for (int t = tid; t < NT; t += blockDim.x) {
        float cv[DOUTD];
        if (t < NT1) {
            int i = t;
            #pragma unroll
            for (int u = 0; u < DOUTD; u++) {
                float acc = 0.f;
                for (int p = 0; p < PP1; p++)
                    acc += u1[((size_t)u * DD + i) * PP1 + p] * wpv[p];
                cv[u] = acc;
            }
        } else if (t < NT1 + NT2) {
            int q = t - NT1;
            int i = 0, cnt = DD;
            while (q >= cnt) { q -= cnt; i++; cnt--; }
            int j = i + q;
            #pragma unroll
            for (int u = 0; u < DOUTD; u++) {
                float acc = 0.f;
                for (int p = 0; p < PP2; p++) {
                    float sym = u2[(((size_t)u * DD + i) * DD + j) * PP2 + p];
                    if (i != j) sym += u2[(((size_t)u * DD + j) * DD + i) * PP2 + p];
                    acc += sym * wpv[PP1 + p];
                }
                cv[u] = acc;
            }
        } else {
            int q = t - NT1 - NT2;
            int i = 0;
            for (;;) {
                int m = DD - i;
                int cnt = m * (m + 1) / 2;
                if (q < cnt) break;
                q -= cnt; i++;
            }
            int j = i;
            for (;;) {
                int cnt = DD - j;
                if (q < cnt) break;
                q -= cnt; j++;
            }
            int k = j + q;
            int pa[6], pb[6], pc[6], np = 0;
            if (i == j && j == k) {
                pa[0]=i; pb[0]=i; pc[0]=i; np = 1;
            } else if (i == j) {
                pa[0]=i; pb[0]=i; pc[0]=k;
                pa[1]=i; pb[1]=k; pc[1]=i;
                pa[2]=k; pb[2]=i; pc[2]=i; np = 3;
            } else if (j == k) {
                pa[0]=i; pb[0]=j; pc[0]=j;
                pa[1]=j; pb[1]=i; pc[1]=j;
                pa[2]=j; pb[2]=j; pc[2]=i; np = 3;
            } else {
                pa[0]=i; pb[0]=j; pc[0]=k;
                pa[1]=i; pb[1]=k; pc[1]=j;
                pa[2]=j; pb[2]=i; pc[2]=k;
                pa[3]=j; pb[3]=k; pc[3]=i;
                pa[4]=k; pb[4]=i; pc[4]=j;
                pa[5]=k; pb[5]=j; pc[5]=i; np = 6;
            }
            #pragma unroll
            for (int u = 0; u < DOUTD; u++) {
                float acc = 0.f;
                for (int m = 0; m < np; m++) {
                    const float* up = u3 + ((((size_t)u * DD + pa[m]) * DD + pb[m]) * DD + pc[m]) * PP3;
                    for (int p = 0; p < PP3; p++)
                        acc += up[p] * wpv[PP1 + PP2 + p];
                }
                cv[u] = acc;
            }
        }
        float2* dst = g_Acoef + (((size_t)(s * CCH + c)) * NT + t) * DOUTD;
        #pragma unroll
        for (int u = 0; u < DOUTD; u++) dst[u] = make_float2(cv[u], cv[u]);
    }
}

// ---------------------------------------------------------------------------
// Main: grid = (N/128, 16), 128 threads. Warp = 1 channel x 128 nodes
// (32 lanes x 2 f32x2 streams). Coefficients smem-broadcast, shared by both
// streams (1 LDS : 4 FFMA2).
// ---------------------------------------------------------------------------
__global__ __launch_bounds__(THREADS, 4) void main_kernel(
    const float* __restrict__ x,
    const int* __restrict__ counts,
    float* __restrict__ out, int N)
{
    extern __shared__ char smemRaw[];
    float2* coefS = (float2*)smemRaw;
    float*  xsS   = (float*)(smemRaw + SMEM_COEF_BYTES);

    const int n0  = blockIdx.x * NPB;
    const int c0  = blockIdx.y * CPB;
    const int tid = threadIdx.x;

    int nLast = n0 + NPB - 1;
    if (nLast > N - 1) nLast = N - 1;
    const int sA = findSpecies(counts, n0);
    const int sB = findSpecies(counts, nLast);
    const bool fast = (sA == sB) && (n0 + NPB <= N);

    // Stage x into [cc][pair][i*2+parity], pair stride 18 words.
    // 64-bit reads at word 18*lane + 2i are bank-conflict-free (18*l mod 32
    // sweeps all even residues; ull grabs the odd partner).
    for (int idx = tid; idx < NPB * CPB * DD; idx += THREADS) {
        int n  = idx / (CPB * DD);
        int r  = idx % (CPB * DD);
        int cc = r / DD;
        int i  = r % DD;
        int gn = n0 + n;
        float v = (gn < N) ? x[((size_t)gn * CCH + (c0 + cc)) * DD + i] : 0.f;
        xsS[(cc * NPAIRS + (n >> 1)) * PAIR_W + 2 * i + (n & 1)] = v;
    }
    if (fast) {
        const float4* src = (const float4*)(g_Acoef + ((size_t)(sA * CCH + c0)) * NT * DOUTD);
        float4* dst = (float4*)coefS;
        for (int idx = tid; idx < SMEM_COEF_F2 / 2; idx += THREADS) dst[idx] = src[idx];
    }
    __syncthreads();

    const int wslot = tid >> 5;     // channel slot 0..3
    const int lane  = tid & 31;
    const int c     = c0 + wslot;

    if (fast) {
        // Stream A: pair=lane (nodes 2l, 2l+1). Stream B: pair=lane+32 (nodes 64+2l, 65+2l)
        ull xvA[DD], xvB[DD];
        const float* xbA = xsS + (wslot * NPAIRS + lane) * PAIR_W;
        const float* xbB = xbA + 32 * PAIR_W;
        #pragma unroll
        for (int i = 0; i < DD; i++) {
            xvA[i] = *(const ull*)(xbA + 2 * i);
            xvB[i] = *(const ull*)(xbB + 2 * i);
        }

        const float2* cf = coefS + (size_t)wslot * NT * DOUTD;
        ull aA0 = 0, aA1 = 0, aA2 = 0, aA3 = 0;
        ull aB0 = 0, aB1 = 0, aB2 = 0, aB3 = 0;
        int t2 = NT1, t3 = NT1 + NT2;
        #pragma unroll
        for (int i = 0; i < DD; i++) {
            {
                const ulonglong2* cp = (const ulonglong2*)(cf + i * DOUTD);
                ulonglong2 lo = cp[0], hi = cp[1];
                aA0 = ffma2(xvA[i], lo.x, aA0);  aB0 = ffma2(xvB[i], lo.x, aB0);
                aA1 = ffma2(xvA[i], lo.y, aA1);  aB1 = ffma2(xvB[i], lo.y, aB1);
                aA2 = ffma2(xvA[i], hi.x, aA2);  aB2 = ffma2(xvB[i], hi.x, aB2);
                aA3 = ffma2(xvA[i], hi.y, aA3);  aB3 = ffma2(xvB[i], hi.y, aB3);
            }
            #pragma unroll
            for (int j = i; j < DD; j++) {
                ull pA = fmul2(xvA[i], xvA[j]);
                ull pB = fmul2(xvB[i], xvB[j]);
                {
                    const ulonglong2* cp = (const ulonglong2*)(cf + t2 * DOUTD);
                    ulonglong2 lo = cp[0], hi = cp[1];
                    aA0 = ffma2(pA, lo.x, aA0);  aB0 = ffma2(pB, lo.x, aB0);
                    aA1 = ffma2(pA, lo.y, aA1);  aB1 = ffma2(pB, lo.y, aB1);
                    aA2 = ffma2(pA, hi.x, aA2);  aB2 = ffma2(pB, hi.x, aB2);
                    aA3 = ffma2(pA, hi.y, aA3);  aB3 = ffma2(pB, hi.y, aB3);
                }
                t2++;
                #pragma unroll
                for (int k = j; k < DD; k++) {
                    ull mA = fmul2(pA, xvA[k]);
                    ull mB = fmul2(pB, xvB[k]);
                    const ulonglong2* cp = (const ulonglong2*)(cf + t3 * DOUTD);
                    ulonglong2 lo = cp[0], hi = cp[1];
                    aA0 = ffma2(mA, lo.x, aA0);  aB0 = ffma2(mB, lo.x, aB0);
                    aA1 = ffma2(mA, lo.y, aA1);  aB1 = ffma2(mB, lo.y, aB1);
                    aA2 = ffma2(mA, hi.x, aA2);  aB2 = ffma2(mB, hi.x, aB2);
                    aA3 = ffma2(mA, hi.y, aA3);  aB3 = ffma2(mB, hi.y, aB3);
                    t3++;
                }
            }
        }

        // Stage results into smem (coef region is dead now), then store coalesced.
        __syncthreads();
        float* outS = (float*)coefS;   // [node][OUT_NODE_W]: 16 data words + 4 pad
        {
            float2 r0 = unpack2(aA0), r1 = unpack2(aA1), r2 = unpack2(aA2), r3 = unpack2(aA3);
            float2 s0 = unpack2(aB0), s1 = unpack2(aB1), s2 = unpack2(aB2), s3 = unpack2(aB3);
            float4* p;
            p = (float4*)(outS + (2 * lane + 0) * OUT_NODE_W + wslot * 4);
            *p = make_float4(r0.x, r1.x, r2.x, r3.x);
            p = (float4*)(outS + (2 * lane + 1) * OUT_NODE_W + wslot * 4);
            *p = make_float4(r0.y, r1.y, r2.y, r3.y);
            p = (float4*)(outS + (64 + 2 * lane + 0) * OUT_NODE_W + wslot * 4);
            *p = make_float4(s0.x, s1.x, s2.x, s3.x);
            p = (float4*)(outS + (64 + 2 * lane + 1) * OUT_NODE_W + wslot * 4);
            *p = make_float4(s0.y, s1.y, s2.y, s3.y);
        }
        __syncthreads();
        // Cooperative coalesced store: 64B contiguous per node (channels c0..c0+3)
        float4* out4 = (float4*)out;
        #pragma unroll
        for (int g = tid; g < NPB * CPB; g += THREADS) {
            int node = g >> 2;
            int q    = g & 3;                     // channel offset within block
            float4 v = *(const float4*)(outS + node * OUT_NODE_W + q * 4);
            out4[(size_t)(n0 + node) * CCH + c0 + q] = v;
        }
    } else {
        // Cold path: boundary / mixed-species blocks. Scalar, coefs from L2.
        #pragma unroll 1
        for (int h = 0; h < 4; h++) {
            int pair   = (h < 2) ? lane : (lane + 32);
            int parity = h & 1;
            int n = n0 + 2 * pair + parity;
            if (n >= N) continue;
            int s = findSpecies(counts, n);
            const float2* cf = g_Acoef + ((size_t)(s * CCH + c)) * NT * DOUTD;
            float xv[DD];
            const float* xb = xsS + (wslot * NPAIRS + pair) * PAIR_W;
            #pragma unroll
            for (int i = 0; i < DD; i++) xv[i] = xb[2 * i + parity];
            float a[DOUTD] = {0.f, 0.f, 0.f, 0.f};
            int t2 = NT1, t3 = NT1 + NT2;
            #pragma unroll 1
            for (int i = 0; i < DD; i++) {
                #pragma unroll
                for (int u = 0; u < DOUTD; u++) a[u] += cf[i * DOUTD + u].x * xv[i];
                #pragma unroll 1
                for (int j = i; j < DD; j++) {
                    float pij = xv[i] * xv[j];
                    #pragma unroll
                    for (int u = 0; u < DOUTD; u++) a[u] += cf[t2 * DOUTD + u].x * pij;
                    t2++;
                    #pragma unroll 1
                    for (int k = j; k < DD; k++) {
                        float m = pij * xv[k];
                        #pragma unroll
                        for (int u = 0; u < DOUTD; u++) a[u] += cf[t3 * DOUTD + u].x * m;
                        t3++;
                    }
                }
            }
            float4* outp = (float4*)out;
            outp[(size_t)n * CCH + c] = make_float4(a[0], a[1], a[2], a[3]);
        }
    }
}

extern "C" void kernel_launch(void* const* d_in, const int* in_sizes, int n_in,
                              void* d_out, int out_size) {
    const float* x     = (const float*)d_in[0];
    const float* w     = (const float*)d_in[1];
    const float* proj  = (const float*)d_in[2];
    const float* u1    = (const float*)d_in[3];
    const float* u2    = (const float*)d_in[4];
    const float* u3    = (const float*)d_in[5];
    const int*   cnts  = (const int*)d_in[6];
    float* out = (float*)d_out;

    int N = in_sizes[0] / (CCH * DD);

    cudaFuncSetAttribute(main_kernel, cudaFuncAttributeMaxDynamicSharedMemorySize, SMEM_BYTES);

    prep_kernel<<<NS * CCH, 256>>>(w, proj, u1, u2, u3);

    dim3 grid((N + NPB - 1) / NPB, CCH / CPB);
    main_kernel<<<grid, THREADS, SMEM_BYTES>>>(x, cnts, out, N);
}